// round 10
// baseline (speedup 1.0000x reference)
#include <cuda_runtime.h>
#include <cuda_fp16.h>

// Problem constants
#define BATCH    8
#define S_BYTES  8192
#define NUM_EMB  384
#define BYTE_DIM 128
#define EMB_DIM  1024
#define NUM_TOK  2048
#define SCALE_F  11.313708498984761f  // sqrt(128)

// proj = SCALE * emb @ W^T, stored fp16: [NUM_EMB, EMB_DIM] (768 KB, L2-resident)
__device__ __half g_proj_h[NUM_EMB * EMB_DIM];
// Segment starts: g_start[b][t] = first byte index s with byte_groups[b][s] >= t
__device__ int g_start[BATCH][NUM_TOK + 1];

// ---------------------------------------------------------------------------
// Kernel 1 (fused): blocks [0,96) GEMM proj = SCALE*emb@W^T (64x64 tile,
// 4x4 microtile, fp32 math, fp16 store); blocks [96,352) segment boundaries.
// ---------------------------------------------------------------------------
#define BM 64
#define BN 64
#define BK 64
#define SPITCH 65
#define GEMM_BLOCKS 96    // (1024/64) x (384/64) = 16 x 6
#define SEG_BLOCKS  256

__global__ __launch_bounds__(256) void prep_kernel(const float* __restrict__ emb,
                                                   const float* __restrict__ W,
                                                   const int* __restrict__ bg) {
    const int tid = threadIdx.x;

    if (blockIdx.x >= GEMM_BLOCKS) {
        // ---- segment boundaries ----
        const int blkk = blockIdx.x - GEMM_BLOCKS;
        const int b    = blkk >> 5;
        const int s    = (blkk & 31) * 256 + tid;
        const int* __restrict__ row = bg + (size_t)b * S_BYTES;

        const int g  = row[s];
        const int gp = (s == 0) ? -1 : row[s - 1];
        for (int t = gp + 1; t <= g; ++t) g_start[b][t] = s;
        if (s == S_BYTES - 1) {
            for (int t = g + 1; t <= NUM_TOK; ++t) g_start[b][t] = S_BYTES;
        }
        return;
    }

    // ---- GEMM: 64x64 tile, BK=64, 4x4 microtile ----
    __shared__ float As[BK][SPITCH];  // [k][m]
    __shared__ float Ws[BK][SPITCH];  // [k][n]

    const int bn = blockIdx.x & 15;   // 0..15
    const int bm = blockIdx.x >> 4;   // 0..5
    const int tx = tid & 15;
    const int ty = tid >> 4;
    const int m0 = ty * 4;
    const int n0 = tx * 4;

    const float* __restrict__ A  = emb + (size_t)(bm * BM) * BYTE_DIM;
    const float* __restrict__ Wt = W   + (size_t)(bn * BN) * BYTE_DIM;

    float acc[4][4] = {};

    for (int kb = 0; kb < BYTE_DIM; kb += BK) {
        #pragma unroll
        for (int i = 0; i < 16; ++i) {
            int f = tid + i * 256;
            int k = f & 63;
            int r = f >> 6;
            As[k][r] = A [(size_t)r * BYTE_DIM + kb + k];
            Ws[k][r] = Wt[(size_t)r * BYTE_DIM + kb + k];
        }
        __syncthreads();

        #pragma unroll 8
        for (int k = 0; k < BK; ++k) {
            float a[4], w[4];
            #pragma unroll
            for (int j = 0; j < 4; ++j) a[j] = As[k][m0 + j];
            #pragma unroll
            for (int j = 0; j < 4; ++j) w[j] = Ws[k][n0 + j];
            #pragma unroll
            for (int i = 0; i < 4; ++i)
                #pragma unroll
                for (int j = 0; j < 4; ++j)
                    acc[i][j] = fmaf(a[i], w[j], acc[i][j]);
        }
        __syncthreads();
    }

    // Store 4x4 microtile as fp16 (4 contiguous halves = one uint2 per row).
    #pragma unroll
    for (int i = 0; i < 4; ++i) {
        __half2 h0 = __floats2half2_rn(acc[i][0] * SCALE_F, acc[i][1] * SCALE_F);
        __half2 h1 = __floats2half2_rn(acc[i][2] * SCALE_F, acc[i][3] * SCALE_F);
        uint2 u;
        u.x = *reinterpret_cast<unsigned int*>(&h0);
        u.y = *reinterpret_cast<unsigned int*>(&h1);
        *reinterpret_cast<uint2*>(
            g_proj_h + (size_t)(bm * BM + m0 + i) * EMB_DIM + bn * BN + n0) = u;
    }
}

// ---------------------------------------------------------------------------
// Kernel 2: ragged mean over fp16 proj rows, warp-per-token, fp16 ACCUMULATE.
// Per byte: 4 LDG.128 (uint4) + 16 HADD2 — ~3x fewer instructions than the
// cvt+FADD version. Indices prefetched 32-at-a-time (coalesced LDG + shfl),
// byte loop unrolled by 2 (8 LDG.128 in flight). fp32 conversion + 1/cnt
// scaling only in the epilogue.
// grid = (NUM_TOK/8, BATCH), block = 256 (8 warps = 8 tokens).
// ---------------------------------------------------------------------------
__global__ __launch_bounds__(256) void pool_kernel(const int* __restrict__ x,
                                                   float* __restrict__ out) {
    const int b    = blockIdx.y;
    const int wid  = threadIdx.x >> 5;
    const int lane = threadIdx.x & 31;
    const int t    = blockIdx.x * 8 + wid;

    const int s0 = g_start[b][t];
    const int s1 = g_start[b][t + 1];
    const int cnt = s1 - s0;

    const int* __restrict__ xr = x + (size_t)b * S_BYTES;
    const uint4* __restrict__ p = reinterpret_cast<const uint4*>(g_proj_h);  // 128/row

    __half2 acc[4][4];
    #pragma unroll
    for (int j = 0; j < 4; ++j)
        #pragma unroll
        for (int k = 0; k < 4; ++k) acc[j][k] = __float2half2_rn(0.f);

    for (int base = s0; base < s1; base += 32) {
        const int nn = min(32, s1 - base);
        int myx = 0;
        if (base + lane < s1) myx = xr[base + lane];  // one coalesced load

        int i = 0;
        for (; i + 2 <= nn; i += 2) {
            const int e0 = __shfl_sync(0xffffffffu, myx, i);
            const int e1 = __shfl_sync(0xffffffffu, myx, i + 1);
            const uint4* __restrict__ p0 = p + (size_t)e0 * (EMB_DIM / 8);
            const uint4* __restrict__ p1 = p + (size_t)e1 * (EMB_DIM / 8);
            uint4 u0[4], u1[4];
            #pragma unroll
            for (int j = 0; j < 4; ++j) u0[j] = p0[lane + 32 * j];
            #pragma unroll
            for (int j = 0; j < 4; ++j) u1[j] = p1[lane + 32 * j];
            #pragma unroll
            for (int j = 0; j < 4; ++j) {
                acc[j][0] = __hadd2(acc[j][0],
                    __hadd2(*reinterpret_cast<__half2*>(&u0[j].x),
                            *reinterpret_cast<__half2*>(&u1[j].x)));
                acc[j][1] = __hadd2(acc[j][1],
                    __hadd2(*reinterpret_cast<__half2*>(&u0[j].y),
                            *reinterpret_cast<__half2*>(&u1[j].y)));
                acc[j][2] = __hadd2(acc[j][2],
                    __hadd2(*reinterpret_cast<__half2*>(&u0[j].z),
                            *reinterpret_cast<__half2*>(&u1[j].z)));
                acc[j][3] = __hadd2(acc[j][3],
                    __hadd2(*reinterpret_cast<__half2*>(&u0[j].w),
                            *reinterpret_cast<__half2*>(&u1[j].w)));
            }
        }
        if (i < nn) {
            const int e = __shfl_sync(0xffffffffu, myx, i);
            const uint4* __restrict__ pr = p + (size_t)e * (EMB_DIM / 8);
            uint4 u[4];
            #pragma unroll
            for (int j = 0; j < 4; ++j) u[j] = pr[lane + 32 * j];
            #pragma unroll
            for (int j = 0; j < 4; ++j) {
                acc[j][0] = __hadd2(acc[j][0], *reinterpret_cast<__half2*>(&u[j].x));
                acc[j][1] = __hadd2(acc[j][1], *reinterpret_cast<__half2*>(&u[j].y));
                acc[j][2] = __hadd2(acc[j][2], *reinterpret_cast<__half2*>(&u[j].z));
                acc[j][3] = __hadd2(acc[j][3], *reinterpret_cast<__half2*>(&u[j].w));
            }
        }
    }

    const float inv = 1.0f / (float)(cnt > 0 ? cnt : 1);

    // uint4 j covers channels [(lane+32j)*8, +8) = two float4s at o[2*(lane+32j)].
    float4* __restrict__ o =
        reinterpret_cast<float4*>(out) + (((size_t)b * NUM_TOK) + t) * (EMB_DIM / 4);
    #pragma unroll
    for (int j = 0; j < 4; ++j) {
        float2 f0 = __half22float2(acc[j][0]);
        float2 f1 = __half22float2(acc[j][1]);
        float2 f2 = __half22float2(acc[j][2]);
        float2 f3 = __half22float2(acc[j][3]);
        float4 v0 = make_float4(f0.x * inv, f0.y * inv, f1.x * inv, f1.y * inv);
        float4 v1 = make_float4(f2.x * inv, f2.y * inv, f3.x * inv, f3.y * inv);
        o[2 * (lane + 32 * j)]     = v0;  // consecutive lanes contiguous 32B
        o[2 * (lane + 32 * j) + 1] = v1;
    }
}

// ---------------------------------------------------------------------------
// Launch
// ---------------------------------------------------------------------------
extern "C" void kernel_launch(void* const* d_in, const int* in_sizes, int n_in,
                              void* d_out, int out_size) {
    const int*   x    = (const int*)  d_in[0];  // [B, S_BYTES] int32
    const int*   bg   = (const int*)  d_in[1];  // [B, S_BYTES] int32 (sorted per row)
    const float* emb  = (const float*)d_in[2];  // [NUM_EMB, BYTE_DIM] fp32
    const float* wout = (const float*)d_in[3];  // [EMB_DIM, BYTE_DIM] fp32
    float* out = (float*)d_out;                 // [B, NUM_TOK, EMB_DIM] fp32

    (void)in_sizes; (void)n_in; (void)out_size;

    prep_kernel<<<GEMM_BLOCKS + SEG_BLOCKS, 256>>>(emb, wout, bg);

    dim3 pgrid(NUM_TOK / 8, BATCH);             // (256, 8) = 2048 blocks
    pool_kernel<<<pgrid, 256>>>(x, out);
}